// round 15
// baseline (speedup 1.0000x reference)
#include <cuda_runtime.h>
#include <cuda_fp16.h>
#include <cstdint>
#include <mma.h>
using namespace nvcuda;

#define DIM 2048
#define NH 32
#define HD 64
#define NB 2
#define NQ 4096
#define NKV 512

// -------- device scratch (allocation-free rule) --------
__device__ __half h_x [(size_t)NB * NQ  * DIM];
__device__ __half h_cx[(size_t)NB * NKV * DIM];
__device__ __half h_wq[(size_t)DIM * DIM];
__device__ __half h_wk[(size_t)DIM * DIM];        // gathered rows h*128+2d
__device__ __half h_wv[(size_t)DIM * DIM];        // gathered rows h*128+2d+1
__device__ __half g_q[(size_t)NB * NH * NQ  * HD]; // rmsnorm(q) * 0.125 * log2(e)
__device__ __half g_k[(size_t)NB * NH * NKV * HD];
__device__ __half g_v[(size_t)NB * NH * HD * NKV]; // (b,h,d,m) transposed

// ===========================================================================
// Conversion prepass, split for stream overlap.
// conv_kv: cx (2048 blocks) + gathered Wk/Wv (4096 blocks) = 6144 blocks
// conv_qx: x (16384 blocks) + Wq (4096 blocks) = 20480 blocks
// ===========================================================================
__global__ __launch_bounds__(256) void conv_kv(
    const float* __restrict__ cx, const float* __restrict__ Wk,
    const float* __restrict__ Wv)
{
    const int bid = blockIdx.x;
    const int t = threadIdx.x;
    if (bid < 2048) {
        size_t i = ((size_t)bid * 256 + t) * 4;
        float4 v = *(const float4*)&cx[i];
        __half o[4] = { __float2half_rn(v.x), __float2half_rn(v.y),
                        __float2half_rn(v.z), __float2half_rn(v.w) };
        *(uint2*)&h_cx[i] = *(uint2*)o;
    } else {
        int i = bid - 2048;
        int j = i >> 1;
        int c = ((i & 1) * 256 + t) * 4;
        int h = j >> 6, d = j & 63;
        int g = h * 128 + 2 * d;
        const float* srcK = (g < DIM) ? (Wk + (size_t)g * DIM) : (Wv + (size_t)(g - DIM) * DIM);
        const float* srcV = (g + 1 < DIM) ? (Wk + (size_t)(g + 1) * DIM)
                                          : (Wv + (size_t)(g + 1 - DIM) * DIM);
        float4 vk = *(const float4*)&srcK[c];
        float4 vv = *(const float4*)&srcV[c];
        __half ok[4] = { __float2half_rn(vk.x), __float2half_rn(vk.y),
                         __float2half_rn(vk.z), __float2half_rn(vk.w) };
        __half ov[4] = { __float2half_rn(vv.x), __float2half_rn(vv.y),
                         __float2half_rn(vv.z), __float2half_rn(vv.w) };
        *(uint2*)&h_wk[(size_t)j * DIM + c] = *(uint2*)ok;
        *(uint2*)&h_wv[(size_t)j * DIM + c] = *(uint2*)ov;
    }
}

__global__ __launch_bounds__(256) void conv_qx(
    const float* __restrict__ x, const float* __restrict__ Wq)
{
    const int bid = blockIdx.x;
    const int t = threadIdx.x;
    const float* src;
    __half* dst;
    size_t i;
    if (bid < 16384) { src = x;  dst = h_x;  i = ((size_t)bid * 256 + t) * 4; }
    else             { src = Wq; dst = h_wq; i = ((size_t)(bid - 16384) * 256 + t) * 4; }
    float4 v = *(const float4*)&src[i];
    __half o[4] = { __float2half_rn(v.x), __float2half_rn(v.y),
                    __float2half_rn(v.z), __float2half_rn(v.w) };
    *(uint2*)&dst[i] = *(uint2*)o;
}

// common cp.async macros
#define CP16(d, s) asm volatile("cp.async.cg.shared.global [%0], [%1], 16;" :: "r"(d), "l"(s))
#define CP_COMMIT() asm volatile("cp.async.commit_group;" ::: "memory")
#define CP_WAIT(n)  asm volatile("cp.async.wait_group %0;" :: "n"(n) : "memory")

// GEMM tiling: K chunk 64 (32 mainloop iterations), row = 128 B data + 16 B pad
#define KC 64
#define KCP2 72                        // halves per smem row (144 B)
#define ROWB 144
#define CLD2 136
#define NCHUNK (DIM / KC)              // 32

#define BM 128
#define ABYTES (BM * ROWB)             // 18432
#define STAGE (2 * ABYTES)             // 36864 (A + B)
#define PROJ_SMEM (2 * STAGE)          // 73728 -> 2 CTAs/SM

// q scale: 1/8 (softmax) * log2(e) (for ex2-based exp)
#define QSCALE 0.18033688011112042f

// ===========================================================================
// Projection GEMM (R12 config, known best). bid_offset splits the 1280-block
// space: kv launch covers bids [0,256), q launch covers [256,1280).
// ===========================================================================
__global__ __launch_bounds__(256, 2) void proj_all(int bid_offset)
{
    extern __shared__ char smraw[];
    uint32_t sbase;
    asm("{ .reg .u64 t; cvta.to.shared.u64 t, %1; cvt.u32.u64 %0, t; }"
        : "=r"(sbase) : "l"(smraw));

    int mode, mt, nt;
    const __half *A, *Bm;
    {
        int bid = blockIdx.x + bid_offset;
        if (bid < 256) {
            int i = bid >> 1;
            mode = 1 + (bid & 1);
            mt = i & 7; nt = i >> 3;
            A = h_cx; Bm = (mode == 1) ? h_wk : h_wv;
        } else {
            int i = bid - 256;
            mode = 0;
            mt = i & 63; nt = i >> 6;
            A = h_x; Bm = h_wq;
        }
    }
    const int m0 = mt * BM;
    const int n0 = nt * BM;
    const int t = threadIdx.x;
    const int warp = t >> 5;
    const int wr = warp & 3;
    const int wc = warp >> 2;

    wmma::fragment<wmma::accumulator, 16, 16, 16, float> c[2][4];
#pragma unroll
    for (int i = 0; i < 2; i++)
#pragma unroll
        for (int j = 0; j < 4; j++) wmma::fill_fragment(c[i][j], 0.0f);

    // per-stage: 1024 A-chunks + 1024 B-chunks of 16 B -> 8 per thread
    const __half* gsrc[8];
    uint32_t doff[8];
#pragma unroll
    for (int j = 0; j < 8; j++) {
        int cidx = t + j * 256;
        if (cidx < 1024) {
            int r = cidx >> 3, sl = cidx & 7;
            gsrc[j] = A + (size_t)(m0 + r) * DIM + sl * 8;
            doff[j] = r * ROWB + sl * 16;
        } else {
            int r = (cidx - 1024) >> 3, sl = cidx & 7;
            gsrc[j] = Bm + (size_t)(n0 + r) * DIM + sl * 8;
            doff[j] = ABYTES + r * ROWB + sl * 16;
        }
    }

#define ISSUE(s, k0) do { \
        _Pragma("unroll") \
        for (int j = 0; j < 8; j++) \
            CP16(sbase + (s) * STAGE + doff[j], gsrc[j] + (k0)); \
        CP_COMMIT(); \
    } while (0)

    ISSUE(0, 0);

    for (int i = 0; i < NCHUNK; i++) {
        const int p = i & 1;
        if (i + 1 < NCHUNK) { ISSUE(p ^ 1, (i + 1) * KC); CP_WAIT(1); }
        else                { CP_WAIT(0); }
        __syncthreads();

        const __half* As = (const __half*)(smraw + p * STAGE);
        const __half* Bs = (const __half*)(smraw + p * STAGE + ABYTES);
#pragma unroll
        for (int ks = 0; ks < KC; ks += 16) {
            wmma::fragment<wmma::matrix_a, 16, 16, 16, __half, wmma::row_major> a0, a1;
            wmma::load_matrix_sync(a0, &As[(wr * 32) * KCP2 + ks], KCP2);
            wmma::load_matrix_sync(a1, &As[(wr * 32 + 16) * KCP2 + ks], KCP2);
#pragma unroll
            for (int nn = 0; nn < 4; nn++) {
                wmma::fragment<wmma::matrix_b, 16, 16, 16, __half, wmma::col_major> b;
                wmma::load_matrix_sync(b, &Bs[(wc * 64 + nn * 16) * KCP2 + ks], KCP2);
                wmma::mma_sync(c[0][nn], a0, b, c[0][nn]);
                wmma::mma_sync(c[1][nn], a1, b, c[1][nn]);
            }
        }
        __syncthreads();
    }

    // epilogue: stage C as half, per-head RMSNorm, write scratch
    __half* Cs = (__half*)smraw;
#pragma unroll
    for (int i = 0; i < 2; i++)
#pragma unroll
        for (int nn = 0; nn < 4; nn++) {
            wmma::fragment<wmma::accumulator, 16, 16, 16, __half> ch;
#pragma unroll
            for (int e = 0; e < ch.num_elements; e++)
                ch.x[e] = __float2half_rn(c[i][nn].x[e]);
            wmma::store_matrix_sync(&Cs[(wr * 32 + i * 16) * CLD2 + wc * 64 + nn * 16],
                                    ch, CLD2, wmma::mem_row_major);
        }
    __syncthreads();

    __shared__ float sscale[BM * 2];
    {
        int row = t >> 1, g = t & 1;
        float s = 1.0f;
        if (mode != 2) {
            const __half* cr = &Cs[row * CLD2 + g * 64];
            float ss = 0.0f;
#pragma unroll
            for (int d = 0; d < 64; d++) { float v = __half2float(cr[d]); ss += v * v; }
            s = rsqrtf(ss * (1.0f / 64.0f) + 1e-6f);
            if (mode == 0) s *= QSCALE;
        }
        sscale[row * 2 + g] = s;
    }
    __syncthreads();

#pragma unroll
    for (int it = 0; it < 16; it++) {
        int f = t + it * 256;
        int row = f >> 5;
        int j = (f & 31) << 2;
        int g = j >> 6;
        int d = j & 63;
        int gi = m0 + row;
        int bb, n;
        if (mode == 0) { bb = gi >> 12; n = gi & 4095; }
        else           { bb = gi >> 9;  n = gi & 511;  }
        int h = (n0 >> 6) + g;
        float sc = sscale[row * 2 + g];
        const __half* cr = &Cs[row * CLD2 + j];
        __half o[4];
#pragma unroll
        for (int u = 0; u < 4; u++)
            o[u] = __float2half_rn(__half2float(cr[u]) * sc);
        if (mode == 2) {
#pragma unroll
            for (int u = 0; u < 4; u++)
                g_v[(((size_t)bb * NH + h) * HD + d + u) * NKV + n] = o[u];
        } else if (mode == 0) {
            *(uint2*)&g_q[(((size_t)bb * NH + h) * NQ + n) * HD + d] = *(uint2*)o;
        } else {
            *(uint2*)&g_k[(((size_t)bb * NH + h) * NKV + n) * HD + d] = *(uint2*)o;
        }
    }
}

// ===========================================================================
// FlashAttention attention — exact R11 (best measured): ATQ=64, 128 threads,
// no-max softmax, ldmatrix.x4, cp.async double buffer.
// ===========================================================================
#define ATQ 64
#define KVT 64
#define TLD 72
#define KVBYTES (KVT * TLD * 2)   // 9216 per buffer

__device__ __forceinline__ void mma16816(float* c, const uint32_t* a,
                                         uint32_t b0, uint32_t b1)
{
    asm volatile(
        "mma.sync.aligned.m16n8k16.row.col.f32.f16.f16.f32 "
        "{%0,%1,%2,%3}, {%4,%5,%6,%7}, {%8,%9}, {%0,%1,%2,%3};"
        : "+f"(c[0]), "+f"(c[1]), "+f"(c[2]), "+f"(c[3])
        : "r"(a[0]), "r"(a[1]), "r"(a[2]), "r"(a[3]), "r"(b0), "r"(b1));
}

__device__ __forceinline__ void ldsm4(uint32_t* b, uint32_t addr)
{
    asm volatile("ldmatrix.sync.aligned.m8n8.x4.shared.b16 {%0,%1,%2,%3}, [%4];"
                 : "=r"(b[0]), "=r"(b[1]), "=r"(b[2]), "=r"(b[3]) : "r"(addr));
}

__device__ __forceinline__ float ex2(float x)
{
    float r;
    asm("ex2.approx.ftz.f32 %0, %1;" : "=f"(r) : "f"(x));
    return r;
}

__global__ __launch_bounds__(128, 4) void attn_fa(float* __restrict__ out)
{
    __shared__ __half Ks[2][KVT * TLD];
    __shared__ __half Vs[2][HD * TLD];

    const int t = threadIdx.x;
    const int warp = t >> 5, lane = t & 31;
    const int group = lane >> 2, tig = lane & 3;
    const int q0 = blockIdx.x * ATQ;
    const int h = blockIdx.y, b = blockIdx.z;

    const __half* qbase = g_q + (((size_t)b * NH + h) * NQ + q0 + warp * 16) * HD;
    const __half* kbase = g_k + ((size_t)b * NH + h) * NKV * HD;
    const __half* vtbase = g_v + ((size_t)b * NH + h) * HD * NKV;

    uint32_t ksb, vsb;
    asm("{ .reg .u64 u; cvta.to.shared.u64 u, %1; cvt.u32.u64 %0, u; }" : "=r"(ksb) : "l"(&Ks[0][0]));
    asm("{ .reg .u64 u; cvta.to.shared.u64 u, %1; cvt.u32.u64 %0, u; }" : "=r"(vsb) : "l"(&Vs[0][0]));

    const uint32_t lm_off = ((uint32_t)(lane & 7) * TLD + (uint32_t)(lane >> 3) * 8) * 2;

    int rr[4], cc[4];
#pragma unroll
    for (int it = 0; it < 4; it++) {
        int f = t + it * 128;
        rr[it] = f >> 3;
        cc[it] = (f & 7) * 8;
    }

#define AISSUE(kt, p) do { \
        _Pragma("unroll") \
        for (int it = 0; it < 4; it++) { \
            CP16(ksb + (p) * KVBYTES + (rr[it] * TLD + cc[it]) * 2, \
                 &kbase[((kt) * 64 + rr[it]) * HD + cc[it]]); \
            CP16(vsb + (p) * KVBYTES + (rr[it] * TLD + cc[it]) * 2, \
                 &vtbase[(size_t)rr[it] * NKV + (kt) * 64 + cc[it]]); \
        } \
        CP_COMMIT(); \
    } while (0)

    uint32_t qa[4][4];
    {
        const __half* qrA = qbase + group * HD;
        const __half* qrB = qbase + (group + 8) * HD;
#pragma unroll
        for (int i = 0; i < 4; i++) {
            qa[i][0] = *(const uint32_t*)&qrA[i * 16 + tig * 2];
            qa[i][1] = *(const uint32_t*)&qrB[i * 16 + tig * 2];
            qa[i][2] = *(const uint32_t*)&qrA[i * 16 + 8 + tig * 2];
            qa[i][3] = *(const uint32_t*)&qrB[i * 16 + 8 + tig * 2];
        }
    }

    AISSUE(0, 0);

    float o[8][4];
#pragma unroll
    for (int j = 0; j < 8; j++)
        o[j][0] = o[j][1] = o[j][2] = o[j][3] = 0.0f;
    float lA = 0.0f, lB = 0.0f;

    for (int kt = 0; kt < 8; kt++) {
        const int p = kt & 1;
        if (kt < 7) { AISSUE(kt + 1, p ^ 1); CP_WAIT(1); }
        else        { CP_WAIT(0); }
        __syncthreads();

        float s[8][4];
#pragma unroll
        for (int j = 0; j < 8; j++) {
            s[j][0] = s[j][1] = s[j][2] = s[j][3] = 0.0f;
            uint32_t base = ksb + p * KVBYTES + (uint32_t)(j * 8 * TLD) * 2 + lm_off;
            uint32_t bm[4];
            ldsm4(bm, base);
            mma16816(s[j], qa[0], bm[0], bm[1]);
            mma16816(s[j], qa[1], bm[2], bm[3]);
            ldsm4(bm, base + 64);
            mma16816(s[j], qa[2], bm[0], bm[1]);
            mma16816(s[j], qa[3], bm[2], bm[3]);
        }

        uint32_t ph[8][2];
        float sumA = 0.0f, sumB = 0.0f;
#pragma unroll
        for (int j = 0; j < 8; j++) {
            float e0 = ex2(s[j][0]);
            float e1 = ex2(s[j][1]);
            float e2 = ex2(s[j][2]);
            float e3 = ex2(s[j][3]);
            sumA += e0 + e1; sumB += e2 + e3;
            __half2 p01 = __floats2half2_rn(e0, e1);
            __half2 p23 = __floats2half2_rn(e2, e3);
            ph[j][0] = *(uint32_t*)&p01;
            ph[j][1] = *(uint32_t*)&p23;
        }
        lA += sumA; lB += sumB;

        uint32_t pa[4][4];
#pragma unroll
        for (int i2 = 0; i2 < 4; i2++) {
            pa[i2][0] = ph[2 * i2][0];     pa[i2][1] = ph[2 * i2][1];
            pa[i2][2] = ph[2 * i2 + 1][0]; pa[i2][3] = ph[2 * i2 + 1][1];
        }
#pragma unroll
        for (int j3 = 0; j3 < 8; j3++) {
            uint32_t base = vsb + p * KVBYTES + (uint32_t)(j3 * 8 * TLD) * 2 + lm_off;
            uint32_t bm[4];
            ldsm4(bm, base);
            mma16816(o[j3], pa[0], bm[0], bm[1]);
            mma16816(o[j3], pa[1], bm[2], bm[3]);
            ldsm4(bm, base + 64);
            mma16816(o[j3], pa[2], bm[0], bm[1]);
            mma16816(o[j3], pa[3], bm[2], bm[3]);
        }
        __syncthreads();
    }

    lA += __shfl_xor_sync(0xffffffffu, lA, 1);
    lA += __shfl_xor_sync(0xffffffffu, lA, 2);
    lB += __shfl_xor_sync(0xffffffffu, lB, 1);
    lB += __shfl_xor_sync(0xffffffffu, lB, 2);
    float rA = 1.0f / lA, rB = 1.0f / lB;

    float* obase = out + ((size_t)b * NQ + q0 + warp * 16) * DIM + h * HD;
#pragma unroll
    for (int j3 = 0; j3 < 8; j3++) {
        float2 vA = { o[j3][0] * rA, o[j3][1] * rA };
        float2 vB = { o[j3][2] * rB, o[j3][3] * rB };
        *(float2*)&obase[(size_t)group * DIM + j3 * 8 + tig * 2] = vA;
        *(float2*)&obase[(size_t)(group + 8) * DIM + j3 * 8 + tig * 2] = vB;
    }
}

// ---------------------------------------------------------------------------
extern "C" void kernel_launch(void* const* d_in, const int* in_sizes, int n_in,
                              void* d_out, int out_size)
{
    const float* x  = (const float*)d_in[0];
    const float* cx = (const float*)d_in[1];
    const float* Wq = (const float*)d_in[2];
    const float* Wk = (const float*)d_in[3];
    const float* Wv = (const float*)d_in[4];
    float* out = (float*)d_out;

    // lazily created on the first (uncaptured) correctness call; reused in capture
    static cudaStream_t s1 = nullptr;
    static cudaEvent_t evFork = nullptr, evQX = nullptr;
    if (s1 == nullptr) {
        cudaStreamCreateWithFlags(&s1, cudaStreamNonBlocking);
        cudaEventCreateWithFlags(&evFork, cudaEventDisableTiming);
        cudaEventCreateWithFlags(&evQX, cudaEventDisableTiming);
        cudaFuncSetAttribute((const void*)proj_all,
                             cudaFuncAttributeMaxDynamicSharedMemorySize, PROJ_SMEM);
    }

    // fork: s1 converts x + Wq (DRAM-bound) while main stream does kv chain
    cudaEventRecord(evFork, 0);
    cudaStreamWaitEvent(s1, evFork, 0);
    conv_qx<<<20480, 256, 0, s1>>>(x, Wq);
    cudaEventRecord(evQX, s1);

    // main stream: kv conversion -> kv projection (overlaps conv_qx)
    conv_kv<<<6144, 256>>>(cx, Wk, Wv);
    proj_all<<<256, 256, PROJ_SMEM>>>(0);

    // join, then q projection and attention
    cudaStreamWaitEvent(0, evQX, 0);
    proj_all<<<1024, 256, PROJ_SMEM>>>(256);
    attn_fa<<<dim3(NQ / ATQ, NH, NB), 128>>>(out);
}

// round 16
// speedup vs baseline: 1.0612x; 1.0612x over previous
#include <cuda_runtime.h>
#include <cuda_fp16.h>
#include <cstdint>
#include <mma.h>
using namespace nvcuda;

#define DIM 2048
#define NH 32
#define HD 64
#define NB 2
#define NQ 4096
#define NKV 512

// -------- device scratch (allocation-free rule) --------
__device__ __half h_x [(size_t)NB * NQ  * DIM];
__device__ __half h_cx[(size_t)NB * NKV * DIM];
__device__ __half h_wq[(size_t)DIM * DIM];
__device__ __half h_wk[(size_t)DIM * DIM];        // gathered rows h*128+2d
__device__ __half h_wv[(size_t)DIM * DIM];        // gathered rows h*128+2d+1
__device__ __half g_q[(size_t)NB * NH * NQ  * HD]; // rmsnorm(q) * 0.125 * log2(e)
__device__ __half g_k[(size_t)NB * NH * NKV * HD];
__device__ __half g_v[(size_t)NB * NH * HD * NKV]; // (b,h,d,m) transposed

// ===========================================================================
// Fused conversion prepass — one launch (known good).
// ===========================================================================
#define CONV_BLOCKS 26624

__global__ __launch_bounds__(256) void conv_all(
    const float* __restrict__ x, const float* __restrict__ cx,
    const float* __restrict__ Wq, const float* __restrict__ Wk,
    const float* __restrict__ Wv)
{
    const int bid = blockIdx.x;
    const int t = threadIdx.x;
    if (bid < 22528) {
        const float* src;
        __half* dst;
        size_t i;
        if (bid < 16384)      { src = x;  dst = h_x;  i = ((size_t)bid * 256 + t) * 4; }
        else if (bid < 18432) { src = cx; dst = h_cx; i = ((size_t)(bid - 16384) * 256 + t) * 4; }
        else                  { src = Wq; dst = h_wq; i = ((size_t)(bid - 18432) * 256 + t) * 4; }
        float4 v = *(const float4*)&src[i];
        __half o[4] = { __float2half_rn(v.x), __float2half_rn(v.y),
                        __float2half_rn(v.z), __float2half_rn(v.w) };
        *(uint2*)&dst[i] = *(uint2*)o;
    } else {
        int i = bid - 22528;
        int j = i >> 1;
        int c = ((i & 1) * 256 + t) * 4;
        int h = j >> 6, d = j & 63;
        int g = h * 128 + 2 * d;
        const float* srcK = (g < DIM) ? (Wk + (size_t)g * DIM) : (Wv + (size_t)(g - DIM) * DIM);
        const float* srcV = (g + 1 < DIM) ? (Wk + (size_t)(g + 1) * DIM)
                                          : (Wv + (size_t)(g + 1 - DIM) * DIM);
        float4 vk = *(const float4*)&srcK[c];
        float4 vv = *(const float4*)&srcV[c];
        __half ok[4] = { __float2half_rn(vk.x), __float2half_rn(vk.y),
                         __float2half_rn(vk.z), __float2half_rn(vk.w) };
        __half ov[4] = { __float2half_rn(vv.x), __float2half_rn(vv.y),
                         __float2half_rn(vv.z), __float2half_rn(vv.w) };
        *(uint2*)&h_wk[(size_t)j * DIM + c] = *(uint2*)ok;
        *(uint2*)&h_wv[(size_t)j * DIM + c] = *(uint2*)ov;
    }
}

// common cp.async macros
#define CP16(d, s) asm volatile("cp.async.cg.shared.global [%0], [%1], 16;" :: "r"(d), "l"(s))
#define CP_COMMIT() asm volatile("cp.async.commit_group;" ::: "memory")
#define CP_WAIT(n)  asm volatile("cp.async.wait_group %0;" :: "n"(n) : "memory")

// GEMM tiling: K chunk 64 (32 mainloop iterations), row = 128 B data + 16 B pad
#define KC 64
#define KCP2 72                        // halves per smem row (144 B)
#define ROWB 144
#define CLD2 136
#define NCHUNK (DIM / KC)              // 32

#define BM 128
#define ABYTES (BM * ROWB)             // 18432
#define STAGE (2 * ABYTES)             // 36864 (A + B)
#define PROJ_SMEM (3 * STAGE)          // 110592 -> 2 CTAs/SM (221 KB < 228 KB)

// q scale: 1/8 (softmax) * log2(e) (for ex2-based exp)
#define QSCALE 0.18033688011112042f

// ===========================================================================
// Fused projection GEMM — one 1280-CTA launch; KC=64, 3-stage ring with
// ISSUE-before-WAIT (issue target (i+2)%3 was last read at i-1 and is
// protected by i-1's trailing barrier) and both barriers kept (R13 lesson:
// never delay prefetch issue behind the barrier).
// ===========================================================================
__global__ __launch_bounds__(256, 2) void proj_all()
{
    extern __shared__ char smraw[];
    uint32_t sbase;
    asm("{ .reg .u64 t; cvta.to.shared.u64 t, %1; cvt.u32.u64 %0, t; }"
        : "=r"(sbase) : "l"(smraw));

    int mode, mt, nt;
    const __half *A, *Bm;
    {
        int bid = blockIdx.x;
        if (bid < 256) {
            int i = bid >> 1;
            mode = 1 + (bid & 1);
            mt = i & 7; nt = i >> 3;
            A = h_cx; Bm = (mode == 1) ? h_wk : h_wv;
        } else {
            int i = bid - 256;
            mode = 0;
            mt = i & 63; nt = i >> 6;
            A = h_x; Bm = h_wq;
        }
    }
    const int m0 = mt * BM;
    const int n0 = nt * BM;
    const int t = threadIdx.x;
    const int warp = t >> 5;
    const int wr = warp & 3;
    const int wc = warp >> 2;

    wmma::fragment<wmma::accumulator, 16, 16, 16, float> c[2][4];
#pragma unroll
    for (int i = 0; i < 2; i++)
#pragma unroll
        for (int j = 0; j < 4; j++) wmma::fill_fragment(c[i][j], 0.0f);

    // per-stage: 1024 A-chunks + 1024 B-chunks of 16 B -> 8 per thread
    const __half* gsrc[8];
    uint32_t doff[8];
#pragma unroll
    for (int j = 0; j < 8; j++) {
        int cidx = t + j * 256;
        if (cidx < 1024) {
            int r = cidx >> 3, sl = cidx & 7;
            gsrc[j] = A + (size_t)(m0 + r) * DIM + sl * 8;
            doff[j] = r * ROWB + sl * 16;
        } else {
            int r = (cidx - 1024) >> 3, sl = cidx & 7;
            gsrc[j] = Bm + (size_t)(n0 + r) * DIM + sl * 8;
            doff[j] = ABYTES + r * ROWB + sl * 16;
        }
    }

#define ISSUE(s, k0) do { \
        _Pragma("unroll") \
        for (int j = 0; j < 8; j++) \
            CP16(sbase + (s) * STAGE + doff[j], gsrc[j] + (k0)); \
        CP_COMMIT(); \
    } while (0)

    ISSUE(0, 0);
    ISSUE(1, KC);

    for (int i = 0; i < NCHUNK; i++) {
        const int p = i % 3;
        if (i + 2 < NCHUNK)      { ISSUE((i + 2) % 3, (i + 2) * KC); CP_WAIT(2); }
        else if (i + 1 < NCHUNK) { CP_WAIT(1); }
        else                     { CP_WAIT(0); }
        __syncthreads();

        const __half* As = (const __half*)(smraw + p * STAGE);
        const __half* Bs = (const __half*)(smraw + p * STAGE + ABYTES);
#pragma unroll
        for (int ks = 0; ks < KC; ks += 16) {
            wmma::fragment<wmma::matrix_a, 16, 16, 16, __half, wmma::row_major> a0, a1;
            wmma::load_matrix_sync(a0, &As[(wr * 32) * KCP2 + ks], KCP2);
            wmma::load_matrix_sync(a1, &As[(wr * 32 + 16) * KCP2 + ks], KCP2);
#pragma unroll
            for (int nn = 0; nn < 4; nn++) {
                wmma::fragment<wmma::matrix_b, 16, 16, 16, __half, wmma::col_major> b;
                wmma::load_matrix_sync(b, &Bs[(wc * 64 + nn * 16) * KCP2 + ks], KCP2);
                wmma::mma_sync(c[0][nn], a0, b, c[0][nn]);
                wmma::mma_sync(c[1][nn], a1, b, c[1][nn]);
            }
        }
        __syncthreads();
    }

    // epilogue: stage C as half, per-head RMSNorm, write scratch
    __half* Cs = (__half*)smraw;
#pragma unroll
    for (int i = 0; i < 2; i++)
#pragma unroll
        for (int nn = 0; nn < 4; nn++) {
            wmma::fragment<wmma::accumulator, 16, 16, 16, __half> ch;
#pragma unroll
            for (int e = 0; e < ch.num_elements; e++)
                ch.x[e] = __float2half_rn(c[i][nn].x[e]);
            wmma::store_matrix_sync(&Cs[(wr * 32 + i * 16) * CLD2 + wc * 64 + nn * 16],
                                    ch, CLD2, wmma::mem_row_major);
        }
    __syncthreads();

    __shared__ float sscale[BM * 2];
    {
        int row = t >> 1, g = t & 1;
        float s = 1.0f;
        if (mode != 2) {
            const __half* cr = &Cs[row * CLD2 + g * 64];
            float ss = 0.0f;
#pragma unroll
            for (int d = 0; d < 64; d++) { float v = __half2float(cr[d]); ss += v * v; }
            s = rsqrtf(ss * (1.0f / 64.0f) + 1e-6f);
            if (mode == 0) s *= QSCALE;
        }
        sscale[row * 2 + g] = s;
    }
    __syncthreads();

#pragma unroll
    for (int it = 0; it < 16; it++) {
        int f = t + it * 256;
        int row = f >> 5;
        int j = (f & 31) << 2;
        int g = j >> 6;
        int d = j & 63;
        int gi = m0 + row;
        int bb, n;
        if (mode == 0) { bb = gi >> 12; n = gi & 4095; }
        else           { bb = gi >> 9;  n = gi & 511;  }
        int h = (n0 >> 6) + g;
        float sc = sscale[row * 2 + g];
        const __half* cr = &Cs[row * CLD2 + j];
        __half o[4];
#pragma unroll
        for (int u = 0; u < 4; u++)
            o[u] = __float2half_rn(__half2float(cr[u]) * sc);
        if (mode == 2) {
#pragma unroll
            for (int u = 0; u < 4; u++)
                g_v[(((size_t)bb * NH + h) * HD + d + u) * NKV + n] = o[u];
        } else if (mode == 0) {
            *(uint2*)&g_q[(((size_t)bb * NH + h) * NQ + n) * HD + d] = *(uint2*)o;
        } else {
            *(uint2*)&g_k[(((size_t)bb * NH + h) * NKV + n) * HD + d] = *(uint2*)o;
        }
    }
}

// ===========================================================================
// FlashAttention attention — exact R11 (best measured): ATQ=64, 128 threads,
// no-max softmax, ldmatrix.x4, cp.async double buffer.
// ===========================================================================
#define ATQ 64
#define KVT 64
#define TLD 72
#define KVBYTES (KVT * TLD * 2)   // 9216 per buffer

__device__ __forceinline__ void mma16816(float* c, const uint32_t* a,
                                         uint32_t b0, uint32_t b1)
{
    asm volatile(
        "mma.sync.aligned.m16n8k16.row.col.f32.f16.f16.f32 "
        "{%0,%1,%2,%3}, {%4,%5,%6,%7}, {%8,%9}, {%0,%1,%2,%3};"
        : "+f"(c[0]), "+f"(c[1]), "+f"(c[2]), "+f"(c[3])
        : "r"(a[0]), "r"(a[1]), "r"(a[2]), "r"(a[3]), "r"(b0), "r"(b1));
}

__device__ __forceinline__ void ldsm4(uint32_t* b, uint32_t addr)
{
    asm volatile("ldmatrix.sync.aligned.m8n8.x4.shared.b16 {%0,%1,%2,%3}, [%4];"
                 : "=r"(b[0]), "=r"(b[1]), "=r"(b[2]), "=r"(b[3]) : "r"(addr));
}

__device__ __forceinline__ float ex2(float x)
{
    float r;
    asm("ex2.approx.ftz.f32 %0, %1;" : "=f"(r) : "f"(x));
    return r;
}

__global__ __launch_bounds__(128, 4) void attn_fa(float* __restrict__ out)
{
    __shared__ __half Ks[2][KVT * TLD];
    __shared__ __half Vs[2][HD * TLD];

    const int t = threadIdx.x;
    const int warp = t >> 5, lane = t & 31;
    const int group = lane >> 2, tig = lane & 3;
    const int q0 = blockIdx.x * ATQ;
    const int h = blockIdx.y, b = blockIdx.z;

    const __half* qbase = g_q + (((size_t)b * NH + h) * NQ + q0 + warp * 16) * HD;
    const __half* kbase = g_k + ((size_t)b * NH + h) * NKV * HD;
    const __half* vtbase = g_v + ((size_t)b * NH + h) * HD * NKV;

    uint32_t ksb, vsb;
    asm("{ .reg .u64 u; cvta.to.shared.u64 u, %1; cvt.u32.u64 %0, u; }" : "=r"(ksb) : "l"(&Ks[0][0]));
    asm("{ .reg .u64 u; cvta.to.shared.u64 u, %1; cvt.u32.u64 %0, u; }" : "=r"(vsb) : "l"(&Vs[0][0]));

    const uint32_t lm_off = ((uint32_t)(lane & 7) * TLD + (uint32_t)(lane >> 3) * 8) * 2;

    int rr[4], cc[4];
#pragma unroll
    for (int it = 0; it < 4; it++) {
        int f = t + it * 128;
        rr[it] = f >> 3;
        cc[it] = (f & 7) * 8;
    }

#define AISSUE(kt, p) do { \
        _Pragma("unroll") \
        for (int it = 0; it < 4; it++) { \
            CP16(ksb + (p) * KVBYTES + (rr[it] * TLD + cc[it]) * 2, \
                 &kbase[((kt) * 64 + rr[it]) * HD + cc[it]]); \
            CP16(vsb + (p) * KVBYTES + (rr[it] * TLD + cc[it]) * 2, \
                 &vtbase[(size_t)rr[it] * NKV + (kt) * 64 + cc[it]]); \
        } \
        CP_COMMIT(); \
    } while (0)

    uint32_t qa[4][4];
    {
        const __half* qrA = qbase + group * HD;
        const __half* qrB = qbase + (group + 8) * HD;
#pragma unroll
        for (int i = 0; i < 4; i++) {
            qa[i][0] = *(const uint32_t*)&qrA[i * 16 + tig * 2];
            qa[i][1] = *(const uint32_t*)&qrB[i * 16 + tig * 2];
            qa[i][2] = *(const uint32_t*)&qrA[i * 16 + 8 + tig * 2];
            qa[i][3] = *(const uint32_t*)&qrB[i * 16 + 8 + tig * 2];
        }
    }

    AISSUE(0, 0);

    float o[8][4];
#pragma unroll
    for (int j = 0; j < 8; j++)
        o[j][0] = o[j][1] = o[j][2] = o[j][3] = 0.0f;
    float lA = 0.0f, lB = 0.0f;

    for (int kt = 0; kt < 8; kt++) {
        const int p = kt & 1;
        if (kt < 7) { AISSUE(kt + 1, p ^ 1); CP_WAIT(1); }
        else        { CP_WAIT(0); }
        __syncthreads();

        float s[8][4];
#pragma unroll
        for (int j = 0; j < 8; j++) {
            s[j][0] = s[j][1] = s[j][2] = s[j][3] = 0.0f;
            uint32_t base = ksb + p * KVBYTES + (uint32_t)(j * 8 * TLD) * 2 + lm_off;
            uint32_t bm[4];
            ldsm4(bm, base);
            mma16816(s[j], qa[0], bm[0], bm[1]);
            mma16816(s[j], qa[1], bm[2], bm[3]);
            ldsm4(bm, base + 64);
            mma16816(s[j], qa[2], bm[0], bm[1]);
            mma16816(s[j], qa[3], bm[2], bm[3]);
        }

        uint32_t ph[8][2];
        float sumA = 0.0f, sumB = 0.0f;
#pragma unroll
        for (int j = 0; j < 8; j++) {
            float e0 = ex2(s[j][0]);
            float e1 = ex2(s[j][1]);
            float e2 = ex2(s[j][2]);
            float e3 = ex2(s[j][3]);
            sumA += e0 + e1; sumB += e2 + e3;
            __half2 p01 = __floats2half2_rn(e0, e1);
            __half2 p23 = __floats2half2_rn(e2, e3);
            ph[j][0] = *(uint32_t*)&p01;
            ph[j][1] = *(uint32_t*)&p23;
        }
        lA += sumA; lB += sumB;

        uint32_t pa[4][4];
#pragma unroll
        for (int i2 = 0; i2 < 4; i2++) {
            pa[i2][0] = ph[2 * i2][0];     pa[i2][1] = ph[2 * i2][1];
            pa[i2][2] = ph[2 * i2 + 1][0]; pa[i2][3] = ph[2 * i2 + 1][1];
        }
#pragma unroll
        for (int j3 = 0; j3 < 8; j3++) {
            uint32_t base = vsb + p * KVBYTES + (uint32_t)(j3 * 8 * TLD) * 2 + lm_off;
            uint32_t bm[4];
            ldsm4(bm, base);
            mma16816(o[j3], pa[0], bm[0], bm[1]);
            mma16816(o[j3], pa[1], bm[2], bm[3]);
            ldsm4(bm, base + 64);
            mma16816(o[j3], pa[2], bm[0], bm[1]);
            mma16816(o[j3], pa[3], bm[2], bm[3]);
        }
        __syncthreads();
    }

    lA += __shfl_xor_sync(0xffffffffu, lA, 1);
    lA += __shfl_xor_sync(0xffffffffu, lA, 2);
    lB += __shfl_xor_sync(0xffffffffu, lB, 1);
    lB += __shfl_xor_sync(0xffffffffu, lB, 2);
    float rA = 1.0f / lA, rB = 1.0f / lB;

    float* obase = out + ((size_t)b * NQ + q0 + warp * 16) * DIM + h * HD;
#pragma unroll
    for (int j3 = 0; j3 < 8; j3++) {
        float2 vA = { o[j3][0] * rA, o[j3][1] * rA };
        float2 vB = { o[j3][2] * rB, o[j3][3] * rB };
        *(float2*)&obase[(size_t)group * DIM + j3 * 8 + tig * 2] = vA;
        *(float2*)&obase[(size_t)(group + 8) * DIM + j3 * 8 + tig * 2] = vB;
    }
}

// ---------------------------------------------------------------------------
extern "C" void kernel_launch(void* const* d_in, const int* in_sizes, int n_in,
                              void* d_out, int out_size)
{
    const float* x  = (const float*)d_in[0];
    const float* cx = (const float*)d_in[1];
    const float* Wq = (const float*)d_in[2];
    const float* Wk = (const float*)d_in[3];
    const float* Wv = (const float*)d_in[4];
    float* out = (float*)d_out;

    cudaFuncSetAttribute((const void*)proj_all,
                         cudaFuncAttributeMaxDynamicSharedMemorySize, PROJ_SMEM);

    conv_all<<<CONV_BLOCKS, 256>>>(x, cx, Wq, Wk, Wv);
    proj_all<<<1280, 256, PROJ_SMEM>>>();
    attn_fa<<<dim3(NQ / ATQ, NH, NB), 128>>>(out);
}

// round 17
// speedup vs baseline: 1.1036x; 1.0399x over previous
#include <cuda_runtime.h>
#include <cuda_fp16.h>
#include <cstdint>
#include <mma.h>
using namespace nvcuda;

#define DIM 2048
#define NH 32
#define HD 64
#define NB 2
#define NQ 4096
#define NKV 512

// -------- device scratch (allocation-free rule) --------
__device__ __half h_x [(size_t)NB * NQ  * DIM];
__device__ __half h_cx[(size_t)NB * NKV * DIM];
__device__ __half h_wq[(size_t)DIM * DIM];
__device__ __half h_wk[(size_t)DIM * DIM];        // gathered rows h*128+2d
__device__ __half h_wv[(size_t)DIM * DIM];        // gathered rows h*128+2d+1
__device__ __half g_q[(size_t)NB * NH * NQ  * HD]; // rmsnorm(q) * 0.125 * log2(e)
__device__ __half g_k[(size_t)NB * NH * NKV * HD];
__device__ __half g_v[(size_t)NB * NH * HD * NKV]; // (b,h,d,m) transposed

// dependency flags (re-zeroed by conv_all every replay)
__device__ int g_qflag[1024];   // q tile i = nt*64 + mt
__device__ int g_kvcnt;         // kv tiles completed (target 256)

// ===========================================================================
// Fused conversion prepass — one launch; block 0 also zeroes the flags.
// ===========================================================================
#define CONV_BLOCKS 26624

__global__ __launch_bounds__(256) void conv_all(
    const float* __restrict__ x, const float* __restrict__ cx,
    const float* __restrict__ Wq, const float* __restrict__ Wk,
    const float* __restrict__ Wv)
{
    const int bid = blockIdx.x;
    const int t = threadIdx.x;
    if (bid == 0) {
        for (int i = t; i < 1024; i += 256) g_qflag[i] = 0;
        if (t == 0) g_kvcnt = 0;
    }
    if (bid < 22528) {
        const float* src;
        __half* dst;
        size_t i;
        if (bid < 16384)      { src = x;  dst = h_x;  i = ((size_t)bid * 256 + t) * 4; }
        else if (bid < 18432) { src = cx; dst = h_cx; i = ((size_t)(bid - 16384) * 256 + t) * 4; }
        else                  { src = Wq; dst = h_wq; i = ((size_t)(bid - 18432) * 256 + t) * 4; }
        float4 v = *(const float4*)&src[i];
        __half o[4] = { __float2half_rn(v.x), __float2half_rn(v.y),
                        __float2half_rn(v.z), __float2half_rn(v.w) };
        *(uint2*)&dst[i] = *(uint2*)o;
    } else {
        int i = bid - 22528;
        int j = i >> 1;
        int c = ((i & 1) * 256 + t) * 4;
        int h = j >> 6, d = j & 63;
        int g = h * 128 + 2 * d;
        const float* srcK = (g < DIM) ? (Wk + (size_t)g * DIM) : (Wv + (size_t)(g - DIM) * DIM);
        const float* srcV = (g + 1 < DIM) ? (Wk + (size_t)(g + 1) * DIM)
                                          : (Wv + (size_t)(g + 1 - DIM) * DIM);
        float4 vk = *(const float4*)&srcK[c];
        float4 vv = *(const float4*)&srcV[c];
        __half ok[4] = { __float2half_rn(vk.x), __float2half_rn(vk.y),
                         __float2half_rn(vk.z), __float2half_rn(vk.w) };
        __half ov[4] = { __float2half_rn(vv.x), __float2half_rn(vv.y),
                         __float2half_rn(vv.z), __float2half_rn(vv.w) };
        *(uint2*)&h_wk[(size_t)j * DIM + c] = *(uint2*)ok;
        *(uint2*)&h_wv[(size_t)j * DIM + c] = *(uint2*)ov;
    }
}

// common cp.async macros
#define CP16(d, s) asm volatile("cp.async.cg.shared.global [%0], [%1], 16;" :: "r"(d), "l"(s))
#define CP_COMMIT() asm volatile("cp.async.commit_group;" ::: "memory")
#define CP_WAIT(n)  asm volatile("cp.async.wait_group %0;" :: "n"(n) : "memory")

// GEMM tiling (R12, best known)
#define KC 64
#define KCP2 72
#define ROWB 144
#define CLD2 136
#define NCHUNK (DIM / KC)              // 32
#define BM 128
#define ABYTES (BM * ROWB)             // 18432
#define STAGE (2 * ABYTES)             // 36864
#define FUSE_SMEM (2 * STAGE)          // 73728 -> 2 CTAs/SM

#define QSCALE 0.18033688011112042f

// attention tiling (R14 256-thread variant)
#define ATQ 128
#define KVT 64
#define TLD 72
#define KVBYTES (KVT * TLD * 2)        // 9216 per buffer

__device__ __forceinline__ void mma16816(float* c, const uint32_t* a,
                                         uint32_t b0, uint32_t b1)
{
    asm volatile(
        "mma.sync.aligned.m16n8k16.row.col.f32.f16.f16.f32 "
        "{%0,%1,%2,%3}, {%4,%5,%6,%7}, {%8,%9}, {%0,%1,%2,%3};"
        : "+f"(c[0]), "+f"(c[1]), "+f"(c[2]), "+f"(c[3])
        : "r"(a[0]), "r"(a[1]), "r"(a[2]), "r"(a[3]), "r"(b0), "r"(b1));
}

__device__ __forceinline__ void ldsm4(uint32_t* b, uint32_t addr)
{
    asm volatile("ldmatrix.sync.aligned.m8n8.x4.shared.b16 {%0,%1,%2,%3}, [%4];"
                 : "=r"(b[0]), "=r"(b[1]), "=r"(b[2]), "=r"(b[3]) : "r"(addr));
}

__device__ __forceinline__ float ex2(float x)
{
    float r;
    asm("ex2.approx.ftz.f32 %0, %1;" : "=f"(r) : "f"(x));
    return r;
}

// ===========================================================================
// Mega-kernel: blocks [0,1280) = proj (R12 body + completion flags),
// blocks [1280,3328) = attention (R14 body + dependency spin).
// Deadlock-free: bid-ordered dispatch => when an attn block is resident,
// every proj block is retired or resident.
// ===========================================================================
__global__ __launch_bounds__(256, 2) void fused_pa(float* __restrict__ out)
{
    extern __shared__ char smraw[];
    const int t = threadIdx.x;

    if (blockIdx.x < 1280) {
        // ------------------------- projection path -------------------------
        uint32_t sbase;
        asm("{ .reg .u64 u; cvta.to.shared.u64 u, %1; cvt.u32.u64 %0, u; }"
            : "=r"(sbase) : "l"(smraw));

        int mode, mt, nt;
        const __half *A, *Bm;
        {
            int bid = blockIdx.x;
            if (bid < 256) {
                int i = bid >> 1;
                mode = 1 + (bid & 1);
                mt = i & 7; nt = i >> 3;
                A = h_cx; Bm = (mode == 1) ? h_wk : h_wv;
            } else {
                int i = bid - 256;
                mode = 0;
                mt = i & 63; nt = i >> 6;
                A = h_x; Bm = h_wq;
            }
        }
        const int m0 = mt * BM;
        const int n0 = nt * BM;
        const int warp = t >> 5;
        const int wr = warp & 3;
        const int wc = warp >> 2;

        wmma::fragment<wmma::accumulator, 16, 16, 16, float> c[2][4];
#pragma unroll
        for (int i = 0; i < 2; i++)
#pragma unroll
            for (int j = 0; j < 4; j++) wmma::fill_fragment(c[i][j], 0.0f);

        const __half* gsrc[8];
        uint32_t doff[8];
#pragma unroll
        for (int j = 0; j < 8; j++) {
            int cidx = t + j * 256;
            if (cidx < 1024) {
                int r = cidx >> 3, sl = cidx & 7;
                gsrc[j] = A + (size_t)(m0 + r) * DIM + sl * 8;
                doff[j] = r * ROWB + sl * 16;
            } else {
                int r = (cidx - 1024) >> 3, sl = cidx & 7;
                gsrc[j] = Bm + (size_t)(n0 + r) * DIM + sl * 8;
                doff[j] = ABYTES + r * ROWB + sl * 16;
            }
        }

#define ISSUE(s, k0) do { \
        _Pragma("unroll") \
        for (int j = 0; j < 8; j++) \
            CP16(sbase + (s) * STAGE + doff[j], gsrc[j] + (k0)); \
        CP_COMMIT(); \
    } while (0)

        ISSUE(0, 0);

        for (int i = 0; i < NCHUNK; i++) {
            const int p = i & 1;
            if (i + 1 < NCHUNK) { ISSUE(p ^ 1, (i + 1) * KC); CP_WAIT(1); }
            else                { CP_WAIT(0); }
            __syncthreads();

            const __half* As = (const __half*)(smraw + p * STAGE);
            const __half* Bs = (const __half*)(smraw + p * STAGE + ABYTES);
#pragma unroll
            for (int ks = 0; ks < KC; ks += 16) {
                wmma::fragment<wmma::matrix_a, 16, 16, 16, __half, wmma::row_major> a0, a1;
                wmma::load_matrix_sync(a0, &As[(wr * 32) * KCP2 + ks], KCP2);
                wmma::load_matrix_sync(a1, &As[(wr * 32 + 16) * KCP2 + ks], KCP2);
#pragma unroll
                for (int nn = 0; nn < 4; nn++) {
                    wmma::fragment<wmma::matrix_b, 16, 16, 16, __half, wmma::col_major> b;
                    wmma::load_matrix_sync(b, &Bs[(wc * 64 + nn * 16) * KCP2 + ks], KCP2);
                    wmma::mma_sync(c[0][nn], a0, b, c[0][nn]);
                    wmma::mma_sync(c[1][nn], a1, b, c[1][nn]);
                }
            }
            __syncthreads();
        }

        __half* Cs = (__half*)smraw;
#pragma unroll
        for (int i = 0; i < 2; i++)
#pragma unroll
            for (int nn = 0; nn < 4; nn++) {
                wmma::fragment<wmma::accumulator, 16, 16, 16, __half> ch;
#pragma unroll
                for (int e = 0; e < ch.num_elements; e++)
                    ch.x[e] = __float2half_rn(c[i][nn].x[e]);
                wmma::store_matrix_sync(&Cs[(wr * 32 + i * 16) * CLD2 + wc * 64 + nn * 16],
                                        ch, CLD2, wmma::mem_row_major);
            }
        __syncthreads();

        __shared__ float sscale[BM * 2];
        {
            int row = t >> 1, g = t & 1;
            float s = 1.0f;
            if (mode != 2) {
                const __half* cr = &Cs[row * CLD2 + g * 64];
                float ss = 0.0f;
#pragma unroll
                for (int d = 0; d < 64; d++) { float v = __half2float(cr[d]); ss += v * v; }
                s = rsqrtf(ss * (1.0f / 64.0f) + 1e-6f);
                if (mode == 0) s *= QSCALE;
            }
            sscale[row * 2 + g] = s;
        }
        __syncthreads();

#pragma unroll
        for (int it = 0; it < 16; it++) {
            int f = t + it * 256;
            int row = f >> 5;
            int j = (f & 31) << 2;
            int g = j >> 6;
            int d = j & 63;
            int gi = m0 + row;
            int bb, n;
            if (mode == 0) { bb = gi >> 12; n = gi & 4095; }
            else           { bb = gi >> 9;  n = gi & 511;  }
            int h = (n0 >> 6) + g;
            float sc = sscale[row * 2 + g];
            const __half* cr = &Cs[row * CLD2 + j];
            __half o[4];
#pragma unroll
            for (int u = 0; u < 4; u++)
                o[u] = __float2half_rn(__half2float(cr[u]) * sc);
            if (mode == 2) {
#pragma unroll
                for (int u = 0; u < 4; u++)
                    g_v[(((size_t)bb * NH + h) * HD + d + u) * NKV + n] = o[u];
            } else if (mode == 0) {
                *(uint2*)&g_q[(((size_t)bb * NH + h) * NQ + n) * HD + d] = *(uint2*)o;
            } else {
                *(uint2*)&g_k[(((size_t)bb * NH + h) * NKV + n) * HD + d] = *(uint2*)o;
            }
        }

        // publish completion (release: per-thread fence, barrier, then flag)
        __threadfence();
        __syncthreads();
        if (t == 0) {
            if (mode == 0) atomicExch(&g_qflag[(blockIdx.x - 256)], 1);
            else           atomicAdd(&g_kvcnt, 1);
        }
        return;
    }

    // --------------------------- attention path ---------------------------
    {
        const int bid2 = blockIdx.x - 1280;
        const int qb = bid2 & 31;            // 32 q-tiles of 128
        const int h = (bid2 >> 5) & 31;
        const int b = bid2 >> 10;
        const int q0 = qb * 128;

        // dependencies: all 256 kv tiles + this (b,h,qb) q tile
        if (t == 0) {
            const int qidx = (h >> 1) * 64 + (b * 32 + qb);
            while (atomicAdd(&g_kvcnt, 0) < 256) {}
            while (atomicAdd(&g_qflag[qidx], 0) == 0) {}
            __threadfence();
        }
        __syncthreads();

        __half* Ks = (__half*)smraw;                       // 2 x KVBYTES
        __half* Vs = (__half*)(smraw + 2 * KVBYTES);       // 2 x KVBYTES

        const int warp = t >> 5, lane = t & 31;
        const int group = lane >> 2, tig = lane & 3;

        const __half* qbase = g_q + (((size_t)b * NH + h) * NQ + q0 + warp * 16) * HD;
        const __half* kbase = g_k + ((size_t)b * NH + h) * NKV * HD;
        const __half* vtbase = g_v + ((size_t)b * NH + h) * HD * NKV;

        uint32_t ksb, vsb;
        asm("{ .reg .u64 u; cvta.to.shared.u64 u, %1; cvt.u32.u64 %0, u; }" : "=r"(ksb) : "l"(Ks));
        asm("{ .reg .u64 u; cvta.to.shared.u64 u, %1; cvt.u32.u64 %0, u; }" : "=r"(vsb) : "l"(Vs));

        const uint32_t lm_off = ((uint32_t)(lane & 7) * TLD + (uint32_t)(lane >> 3) * 8) * 2;

        int rr[2], cc[2];
#pragma unroll
        for (int it = 0; it < 2; it++) {
            int f = t + it * 256;
            rr[it] = f >> 3;
            cc[it] = (f & 7) * 8;
        }

#define AISSUE(kt, p) do { \
        _Pragma("unroll") \
        for (int it = 0; it < 2; it++) { \
            CP16(ksb + (p) * KVBYTES + (rr[it] * TLD + cc[it]) * 2, \
                 &kbase[((kt) * 64 + rr[it]) * HD + cc[it]]); \
            CP16(vsb + (p) * KVBYTES + (rr[it] * TLD + cc[it]) * 2, \
                 &vtbase[(size_t)rr[it] * NKV + (kt) * 64 + cc[it]]); \
        } \
        CP_COMMIT(); \
    } while (0)

        uint32_t qa[4][4];
        {
            const __half* qrA = qbase + group * HD;
            const __half* qrB = qbase + (group + 8) * HD;
#pragma unroll
            for (int i = 0; i < 4; i++) {
                qa[i][0] = *(const uint32_t*)&qrA[i * 16 + tig * 2];
                qa[i][1] = *(const uint32_t*)&qrB[i * 16 + tig * 2];
                qa[i][2] = *(const uint32_t*)&qrA[i * 16 + 8 + tig * 2];
                qa[i][3] = *(const uint32_t*)&qrB[i * 16 + 8 + tig * 2];
            }
        }

        AISSUE(0, 0);

        float o[8][4];
#pragma unroll
        for (int j = 0; j < 8; j++)
            o[j][0] = o[j][1] = o[j][2] = o[j][3] = 0.0f;
        float lA = 0.0f, lB = 0.0f;

        for (int kt = 0; kt < 8; kt++) {
            const int p = kt & 1;
            if (kt < 7) { AISSUE(kt + 1, p ^ 1); CP_WAIT(1); }
            else        { CP_WAIT(0); }
            __syncthreads();

            float s[8][4];
#pragma unroll
            for (int j = 0; j < 8; j++) {
                s[j][0] = s[j][1] = s[j][2] = s[j][3] = 0.0f;
                uint32_t base = ksb + p * KVBYTES + (uint32_t)(j * 8 * TLD) * 2 + lm_off;
                uint32_t bm[4];
                ldsm4(bm, base);
                mma16816(s[j], qa[0], bm[0], bm[1]);
                mma16816(s[j], qa[1], bm[2], bm[3]);
                ldsm4(bm, base + 64);
                mma16816(s[j], qa[2], bm[0], bm[1]);
                mma16816(s[j], qa[3], bm[2], bm[3]);
            }

            uint32_t ph[8][2];
            float sumA = 0.0f, sumB = 0.0f;
#pragma unroll
            for (int j = 0; j < 8; j++) {
                float e0 = ex2(s[j][0]);
                float e1 = ex2(s[j][1]);
                float e2 = ex2(s[j][2]);
                float e3 = ex2(s[j][3]);
                sumA += e0 + e1; sumB += e2 + e3;
                __half2 p01 = __floats2half2_rn(e0, e1);
                __half2 p23 = __floats2half2_rn(e2, e3);
                ph[j][0] = *(uint32_t*)&p01;
                ph[j][1] = *(uint32_t*)&p23;
            }
            lA += sumA; lB += sumB;

            uint32_t pa[4][4];
#pragma unroll
            for (int i2 = 0; i2 < 4; i2++) {
                pa[i2][0] = ph[2 * i2][0];     pa[i2][1] = ph[2 * i2][1];
                pa[i2][2] = ph[2 * i2 + 1][0]; pa[i2][3] = ph[2 * i2 + 1][1];
            }
#pragma unroll
            for (int j3 = 0; j3 < 8; j3++) {
                uint32_t base = vsb + p * KVBYTES + (uint32_t)(j3 * 8 * TLD) * 2 + lm_off;
                uint32_t bm[4];
                ldsm4(bm, base);
                mma16816(o[j3], pa[0], bm[0], bm[1]);
                mma16816(o[j3], pa[1], bm[2], bm[3]);
                ldsm4(bm, base + 64);
                mma16816(o[j3], pa[2], bm[0], bm[1]);
                mma16816(o[j3], pa[3], bm[2], bm[3]);
            }
            __syncthreads();
        }

        lA += __shfl_xor_sync(0xffffffffu, lA, 1);
        lA += __shfl_xor_sync(0xffffffffu, lA, 2);
        lB += __shfl_xor_sync(0xffffffffu, lB, 1);
        lB += __shfl_xor_sync(0xffffffffu, lB, 2);
        float rA = 1.0f / lA, rB = 1.0f / lB;

        float* obase = out + ((size_t)b * NQ + q0 + warp * 16) * DIM + h * HD;
#pragma unroll
        for (int j3 = 0; j3 < 8; j3++) {
            float2 vA = { o[j3][0] * rA, o[j3][1] * rA };
            float2 vB = { o[j3][2] * rB, o[j3][3] * rB };
            *(float2*)&obase[(size_t)group * DIM + j3 * 8 + tig * 2] = vA;
            *(float2*)&obase[(size_t)(group + 8) * DIM + j3 * 8 + tig * 2] = vB;
        }
    }
}

// ---------------------------------------------------------------------------
extern "C" void kernel_launch(void* const* d_in, const int* in_sizes, int n_in,
                              void* d_out, int out_size)
{
    const float* x  = (const float*)d_in[0];
    const float* cx = (const float*)d_in[1];
    const float* Wq = (const float*)d_in[2];
    const float* Wk = (const float*)d_in[3];
    const float* Wv = (const float*)d_in[4];
    float* out = (float*)d_out;

    cudaFuncSetAttribute((const void*)fused_pa,
                         cudaFuncAttributeMaxDynamicSharedMemorySize, FUSE_SMEM);

    conv_all<<<CONV_BLOCKS, 256>>>(x, cx, Wq, Wk, Wv);
    // one launch: 1280 proj blocks then 2048 attention blocks (flag-gated)
    fused_pa<<<3328, 256, FUSE_SMEM>>>(out);
}